// round 14
// baseline (speedup 1.0000x reference)
#include <cuda_runtime.h>
#include <math.h>

#define BN 16
#define DD 512
#define TT 2048
#define CC 20
#define KK 7
#define FF (CC*KK)            // 140
#define PT 2048
#define TS 32                 // similarity tile
#define EPSV 1e-8f
#define BIGV 1e9f
#define THSIM 0.5f
#define THDIF 0.1f
#define SIM_BLOCKS 576

// -------- scratch (static device globals; no runtime allocation) --------
__device__ float    g_Et[(size_t)BN*DD*PT];   // transposed gathered points [b][d][p]
__device__ int      g_fg_idx[BN*FF];
__device__ int      g_slotmap[BN*TT];
__device__ int      g_sw[BN*PT];
__device__ unsigned char g_sfg[BN*PT];
__device__ unsigned char g_sbg[BN*PT];
__device__ int      g_Nb[BN];
__device__ int      g_bgcnt[BN];
__device__ int      g_sumw[BN];
__device__ int      g_tiles[BN];
__device__ unsigned g_minff[BN*PT];
__device__ unsigned g_maxfb[BN*PT];
__device__ unsigned g_minbb[BN*PT];
__device__ unsigned g_maxbf[BN*PT];
__device__ float    g_perbatch[BN];
__device__ int      g_ticket;

__device__ __forceinline__ unsigned fenc(float f) {
    unsigned u = __float_as_uint(f);
    return (u & 0x80000000u) ? ~u : (u | 0x80000000u);
}
__device__ __forceinline__ float fdec(unsigned x) {
    return (x & 0x80000000u) ? __uint_as_float(x ^ 0x80000000u) : __uint_as_float(~x);
}

// -------- single-pass top-7: per-thread sorted list + tournament merge --------
__global__ void k_topk(const float* __restrict__ cas) {
    int c = blockIdx.x, b = blockIdx.y, tid = threadIdx.x;
    const float* row = cas + ((size_t)b * CC + c) * TT;

    float lv[KK]; int li[KK];
#pragma unroll
    for (int j = 0; j < KK; j++) { lv[j] = -INFINITY; li[j] = 0x7fffffff; }
#pragma unroll
    for (int i = 0; i < 8; i++) {
        int t = tid + i * 256;
        float cv = row[t]; int ci = t;
#pragma unroll
        for (int j = 0; j < KK; j++) {
            bool better = (cv > lv[j]) || (cv == lv[j] && ci < li[j]);
            if (better) { float tv = lv[j]; int ti = li[j]; lv[j] = cv; li[j] = ci; cv = tv; ci = ti; }
        }
    }

    __shared__ float sv[256][KK];
    __shared__ int   si[256][KK];
#pragma unroll
    for (int j = 0; j < KK; j++) { sv[tid][j] = lv[j]; si[tid][j] = li[j]; }

    for (int s = 128; s > 0; s >>= 1) {
        __syncthreads();
        if (tid < s) {
            float mv[KK]; int mi[KK];
            int ia = 0, ib = 0;
#pragma unroll
            for (int j = 0; j < KK; j++) {
                float va = sv[tid][ia],     vb = sv[tid + s][ib];
                int   xa = si[tid][ia],     xb = si[tid + s][ib];
                bool takeA = (va > vb) || (va == vb && xa < xb);
                if (takeA) { mv[j] = va; mi[j] = xa; ia++; }
                else       { mv[j] = vb; mi[j] = xb; ib++; }
            }
#pragma unroll
            for (int j = 0; j < KK; j++) { sv[tid][j] = mv[j]; si[tid][j] = mi[j]; }
        }
    }
    __syncthreads();
    if (tid < KK) g_fg_idx[b * FF + c * KK + tid] = si[0][tid];
}

// -------- prep: unique-point slots, flags, weights, reduction init --------
__global__ void k_prep(const int* __restrict__ click, const int* __restrict__ label,
                       const int* __restrict__ clsnum) {
    int b = blockIdx.x, tid = threadIdx.x;
    int cn = clsnum ? clsnum[0] : CC;
    __shared__ int w[TT];
    __shared__ int woff[8];
    __shared__ int sbase, sbg;
    for (int t = tid; t < TT; t += 256) w[t] = 0;
    unsigned encBig = fenc(BIGV), encNeg = fenc(-BIGV);
    for (int p = tid; p < PT; p += 256) {
        g_minff[b * PT + p] = encBig;
        g_maxfb[b * PT + p] = encNeg;
        g_minbb[b * PT + p] = encBig;
        g_maxbf[b * PT + p] = encNeg;
    }
    if (tid == 0) { sbase = 0; sbg = 0; }
    __syncthreads();
    for (int i = tid; i < FF; i += 256) {
        int c = i / KK;
        if (label[b * CC + c] == 1) atomicAdd(&w[g_fg_idx[b * FF + i]], 1);
    }
    __syncthreads();
    for (int chunk = 0; chunk < TT; chunk += 256) {
        int t = chunk + tid;
        int bg  = (click[b * TT + t] == cn) ? 1 : 0;
        int wt  = w[t];
        int sel = (bg || wt > 0) ? 1 : 0;
        unsigned ball = __ballot_sync(0xffffffffu, sel);
        unsigned ballbg = __ballot_sync(0xffffffffu, bg);
        int wi = tid >> 5, lane = tid & 31;
        if (lane == 0) { woff[wi] = __popc(ball); atomicAdd(&sbg, __popc(ballbg)); }
        __syncthreads();
        if (tid == 0) {
            int s = sbase;
            for (int i = 0; i < 8; i++) { int cc2 = woff[i]; woff[i] = s; s += cc2; }
            sbase = s;
        }
        __syncthreads();
        if (sel) {
            int pos = woff[wi] + __popc(ball & ((1u << lane) - 1u));
            g_slotmap[b * TT + t] = pos;
            g_sw[b * PT + pos] = wt;
            g_sfg[b * PT + pos] = (wt > 0) ? 1 : 0;
            g_sbg[b * PT + pos] = (unsigned char)bg;
        } else {
            g_slotmap[b * TT + t] = -1;
        }
        __syncthreads();
    }
    if (tid == 0) {
        int numpos = 0;
        for (int c = 0; c < CC; c++) numpos += (label[b * CC + c] == 1) ? 1 : 0;
        g_sumw[b]  = KK * numpos;
        g_bgcnt[b] = sbg;
        g_Nb[b]    = sbase;
        g_tiles[b] = (sbase + TS - 1) / TS;
    }
}

// -------- transpose-gather: 4 d-rows/block, 8 loads in flight, shared slotmap --------
__global__ void k_gatherT(const float* __restrict__ emb) {
    int b = blockIdx.y, tid = threadIdx.x;
    int d0 = blockIdx.x * 4;
    __shared__ int smap[TT];
#pragma unroll
    for (int i = 0; i < 8; i++) smap[tid + i * 256] = g_slotmap[b * TT + tid + i * 256];
    __syncthreads();

    const float4* src = (const float4*)(emb + ((size_t)b * DD + d0) * TT);
    float4 v[8];
#pragma unroll
    for (int dd = 0; dd < 4; dd++) {
#pragma unroll
        for (int it = 0; it < 2; it++)
            v[dd * 2 + it] = src[dd * (TT / 4) + tid + it * 256];
    }
    int sA[4], sB[4];
    {
        int t0 = tid * 4, t1 = (tid + 256) * 4;
#pragma unroll
        for (int j = 0; j < 4; j++) { sA[j] = smap[t0 + j]; sB[j] = smap[t1 + j]; }
    }
#pragma unroll
    for (int dd = 0; dd < 4; dd++) {
        float* dst = g_Et + ((size_t)b * DD + d0 + dd) * PT;
        float4 a = v[dd * 2], c = v[dd * 2 + 1];
        if (sA[0] >= 0) dst[sA[0]] = a.x;
        if (sA[1] >= 0) dst[sA[1]] = a.y;
        if (sA[2] >= 0) dst[sA[2]] = a.z;
        if (sA[3] >= 0) dst[sA[3]] = a.w;
        if (sB[0] >= 0) dst[sB[0]] = c.x;
        if (sB[1] >= 0) dst[sB[1]] = c.y;
        if (sB[2] >= 0) dst[sB[2]] = c.z;
        if (sB[3] >= 0) dst[sB[3]] = c.w;
    }
}

// -------- routing helper: one row-quad (4 cosines) per thread --------
__device__ __forceinline__ void route_quad(const float cs[4], int b, int ri, bool rvalid,
                                           const int cfg[4], const int cbg[4], int tx) {
    float vFF = BIGV, vBF = -BIGV, vFB = -BIGV, vBB = BIGV;
#pragma unroll
    for (int j = 0; j < 4; j++) {
        if (cfg[j]) { vFF = fminf(vFF, cs[j]); vBF = fmaxf(vBF, cs[j]); }
        if (cbg[j]) { vFB = fmaxf(vFB, cs[j]); vBB = fminf(vBB, cs[j]); }
    }
#pragma unroll
    for (int m = 4; m > 0; m >>= 1) {
        vFF = fminf(vFF, __shfl_xor_sync(0xffffffffu, vFF, m));
        vBF = fmaxf(vBF, __shfl_xor_sync(0xffffffffu, vBF, m));
        vFB = fmaxf(vFB, __shfl_xor_sync(0xffffffffu, vFB, m));
        vBB = fminf(vBB, __shfl_xor_sync(0xffffffffu, vBB, m));
    }
    if (tx == 0 && rvalid) {
        if (g_sfg[b * PT + ri]) {
            atomicMin(&g_minff[b * PT + ri], fenc(vFF));
            atomicMax(&g_maxfb[b * PT + ri], fenc(vFB));
        }
        if (g_sbg[b * PT + ri]) {
            atomicMax(&g_maxbf[b * PT + ri], fenc(vBF));
            atomicMin(&g_minbb[b * PT + ri], fenc(vBB));
        }
    }
}

// -------- fused symmetric tiled similarity:
//          smem double-buffer, dependency-free cooperative LDG, 2x2 micro --------
__global__ void __launch_bounds__(256) k_sim() {
    __shared__ float  Sa[2][64][32];        // 16 KB
    __shared__ float  Sb[2][64][32];        // 16 KB
    __shared__ float  comb[TS][TS + 1];     // 4.2 KB
    __shared__ float4 sqA4[256];            // 4 KB  per-thread A sq partials
    __shared__ float4 sqB4[256];            // 4 KB
    __shared__ float  nrmA[TS], nrmB[TS];
    __shared__ int    s_off[BN + 1];

    int tid = threadIdx.x;
    int tx2 = tid & 15, ty2 = tid >> 4;     // 2x2 micro-tile coords
    int qi  = tid & 7;                      // load: quad within 32-point row
    int dL  = tid >> 3;                     // load: d-slot 0..31 (second at +32)
    int tx  = tid & 7;                      // epilogue col-group

    if (tid == 0) {
        int off = 0;
        for (int b = 0; b < BN; b++) { s_off[b] = off; int t = g_tiles[b]; off += t * (t + 1) / 2; }
        s_off[BN] = off;
    }
    __syncthreads();
    int total = s_off[BN];

    for (int item = blockIdx.x; item < total; item += gridDim.x) {
        int b = 0;
        while (b < BN - 1 && item >= s_off[b + 1]) b++;
        int local = item - s_off[b];
        int tiles = g_tiles[b];
        int rt = 0, rem = local;
        while (rem >= tiles - rt) { rem -= tiles - rt; rt++; }
        int ct = rt + rem;
        int Nb = g_Nb[b];
        int rowb = rt * TS, colb = ct * TS;

        const float* Eb = g_Et + (size_t)b * DD * PT;
        const float* pA = Eb + rowb + qi * 4;   // + d*PT
        const float* pB = Eb + colb + qi * 4;

        float acc00 = 0.f, acc01 = 0.f, acc10 = 0.f, acc11 = 0.f;
        float4 sqa = {0.f, 0.f, 0.f, 0.f}, sqb = {0.f, 0.f, 0.f, 0.f};
        float4 A0, A1, B0, B1;

        // prologue: chunk 0 -> buf 0
        {
            size_t o0 = (size_t)dL * PT, o1 = (size_t)(dL + 32) * PT;
            A0 = *(const float4*)(pA + o0); A1 = *(const float4*)(pA + o1);
            B0 = *(const float4*)(pB + o0); B1 = *(const float4*)(pB + o1);
            *(float4*)&Sa[0][dL][qi * 4] = A0; *(float4*)&Sa[0][dL + 32][qi * 4] = A1;
            *(float4*)&Sb[0][dL][qi * 4] = B0; *(float4*)&Sb[0][dL + 32][qi * 4] = B1;
            sqa.x += A0.x * A0.x; sqa.y += A0.y * A0.y; sqa.z += A0.z * A0.z; sqa.w += A0.w * A0.w;
            sqa.x += A1.x * A1.x; sqa.y += A1.y * A1.y; sqa.z += A1.z * A1.z; sqa.w += A1.w * A1.w;
            sqb.x += B0.x * B0.x; sqb.y += B0.y * B0.y; sqb.z += B0.z * B0.z; sqb.w += B0.w * B0.w;
            sqb.x += B1.x * B1.x; sqb.y += B1.y * B1.y; sqb.z += B1.z * B1.z; sqb.w += B1.w * B1.w;
        }
        __syncthreads();

#pragma unroll 1
        for (int c = 0; c < 8; c++) {
            int buf = c & 1;
            if (c < 7) {   // prefetch chunk c+1 (independent LDGs, batched by ptxas)
                size_t o0 = (size_t)((c + 1) * 64 + dL) * PT;
                size_t o1 = (size_t)((c + 1) * 64 + dL + 32) * PT;
                A0 = *(const float4*)(pA + o0); A1 = *(const float4*)(pA + o1);
                B0 = *(const float4*)(pB + o0); B1 = *(const float4*)(pB + o1);
            }
            // compute chunk c from smem
            const float* sa = &Sa[buf][0][ty2 * 2];
            const float* sb = &Sb[buf][0][tx2 * 2];
#pragma unroll 16
            for (int dk = 0; dk < 64; dk++) {
                float2 a = *(const float2*)(sa + dk * 32);
                float2 v = *(const float2*)(sb + dk * 32);
                acc00 += a.x * v.x; acc01 += a.x * v.y;
                acc10 += a.y * v.x; acc11 += a.y * v.y;
            }
            if (c < 7) {
                __syncthreads();   // all readers of buf^1 (chunk c-1) done
                *(float4*)&Sa[buf ^ 1][dL][qi * 4] = A0; *(float4*)&Sa[buf ^ 1][dL + 32][qi * 4] = A1;
                *(float4*)&Sb[buf ^ 1][dL][qi * 4] = B0; *(float4*)&Sb[buf ^ 1][dL + 32][qi * 4] = B1;
                sqa.x += A0.x * A0.x; sqa.y += A0.y * A0.y; sqa.z += A0.z * A0.z; sqa.w += A0.w * A0.w;
                sqa.x += A1.x * A1.x; sqa.y += A1.y * A1.y; sqa.z += A1.z * A1.z; sqa.w += A1.w * A1.w;
                sqb.x += B0.x * B0.x; sqb.y += B0.y * B0.y; sqb.z += B0.z * B0.z; sqb.w += B0.w * B0.w;
                sqb.x += B1.x * B1.x; sqb.y += B1.y * B1.y; sqb.z += B1.z * B1.z; sqb.w += B1.w * B1.w;
                __syncthreads();   // new chunk visible before its compute
            }
        }

        // epilogue: deposit accs + sq partials
        comb[2 * ty2    ][2 * tx2    ] = acc00;
        comb[2 * ty2    ][2 * tx2 + 1] = acc01;
        comb[2 * ty2 + 1][2 * tx2    ] = acc10;
        comb[2 * ty2 + 1][2 * tx2 + 1] = acc11;
        sqA4[tid] = sqa;
        sqB4[tid] = sqb;
        __syncthreads();

        // norms: point p gets fixed-order fold over threads tid = (p>>2) + 8k, k asc
        if (tid < 64) {
            int side = tid >> 5;
            int p = tid & 31;
            int q = p >> 2, j = p & 3;
            const float4* src = side ? sqB4 : sqA4;
            float s = 0.f;
#pragma unroll
            for (int k = 0; k < 32; k++)
                s += ((const float*)&src[q + 8 * k])[j];
            if (side) nrmB[p] = sqrtf(s);
            else      nrmA[p] = sqrtf(s);
        }
        __syncthreads();

        // route pass 1: rows = A-points, cols = B-points
        {
            int lr = tid >> 3;
            int ri = rowb + lr;
            float nr = nrmA[lr];
            float cs[4]; int cfg[4], cbg[4];
#pragma unroll
            for (int j = 0; j < 4; j++) {
                int lc = 4 * tx + j;
                int c = colb + lc;
                bool cok = (c < Nb);
                cs[j] = comb[lr][lc] / fmaxf(nr * nrmB[lc], EPSV);
                cfg[j] = cok && g_sfg[b * PT + c];
                cbg[j] = cok && g_sbg[b * PT + c];
            }
            route_quad(cs, b, ri, ri < Nb, cfg, cbg, tx);
        }
        // route pass 2 (off-diagonal): rows = B-points, cols = A-points
        if (rt != ct) {
            int lr = tid >> 3;
            int ri = colb + lr;
            float nr = nrmB[lr];
            float cs[4]; int cfg[4], cbg[4];
#pragma unroll
            for (int j = 0; j < 4; j++) {
                int lc = 4 * tx + j;
                int c = rowb + lc;
                bool cok = (c < Nb);
                cs[j] = comb[lc][lr] / fmaxf(nr * nrmA[lc], EPSV);
                cfg[j] = cok && g_sfg[b * PT + c];
                cbg[j] = cok && g_sbg[b * PT + c];
            }
            route_quad(cs, b, ri, ri < Nb, cfg, cbg, tx);
        }
        __syncthreads();   // protect smem before next item
    }
}

// -------- per-batch weighted means + fused final (last-block ticket) --------
__global__ void k_batch(float* __restrict__ out) {
    int b = blockIdx.x, tid = threadIdx.x;
    int Nb = g_Nb[b];
    float sff = 0.f, sfb = 0.f, sbb = 0.f, sbf = 0.f;
    for (int p = tid; p < Nb; p += 256) {
        if (g_sfg[b * PT + p]) {
            float wv = (float)g_sw[b * PT + p];
            sff += wv * fmaxf(THSIM - fdec(g_minff[b * PT + p]), 0.f);
            sfb += wv * fmaxf(fdec(g_maxfb[b * PT + p]) - THDIF, 0.f);
        }
        if (g_sbg[b * PT + p]) {
            sbb += fmaxf(THSIM - fdec(g_minbb[b * PT + p]), 0.f);
            sbf += fmaxf(fdec(g_maxbf[b * PT + p]) - THDIF, 0.f);
        }
    }
    __shared__ float r1[256], r2[256], r3[256], r4[256];
    __shared__ int s_last;
    r1[tid] = sff; r2[tid] = sfb; r3[tid] = sbb; r4[tid] = sbf;
    __syncthreads();
    for (int s = 128; s > 0; s >>= 1) {
        if (tid < s) {
            r1[tid] += r1[tid + s]; r2[tid] += r2[tid + s];
            r3[tid] += r3[tid + s]; r4[tid] += r4[tid + s];
        }
        __syncthreads();
    }
    if (tid == 0) {
        int cnt = g_bgcnt[b];
        float denf = fmaxf((float)g_sumw[b], 1.f);
        float denb = fmaxf((float)cnt, 1.f);
        float loss = r1[0] / denf + r2[0] / denf + r3[0] / denb + r4[0] / denb;
        g_perbatch[b] = (cnt > 0) ? loss : 0.f;
        __threadfence();
        int old = atomicAdd(&g_ticket, 1);
        s_last = (old == BN - 1) ? 1 : 0;
    }
    __syncthreads();
    if (s_last && tid == 0) {
        volatile float* pb = g_perbatch;
        float s = 0.f; int c = 0;
        for (int bb = 0; bb < BN; bb++) { s += pb[bb]; if (g_bgcnt[bb] > 0) c++; }
        out[0] = s / fmaxf((float)c, 1.f);
        g_ticket = 0;   // reset for next graph replay
    }
}

extern "C" void kernel_launch(void* const* d_in, const int* in_sizes, int n_in,
                              void* d_out, int out_size) {
    const float* emb    = (const float*)d_in[0];
    const float* cas    = (const float*)d_in[1];
    const int*   click  = (const int*)d_in[2];
    const int*   label  = (const int*)d_in[3];
    const int*   clsnum = (n_in >= 5) ? (const int*)d_in[4] : nullptr;

    k_topk   <<<dim3(CC, BN), 256>>>(cas);
    k_prep   <<<BN, 256>>>(click, label, clsnum);
    k_gatherT<<<dim3(DD / 4, BN), 256>>>(emb);
    k_sim    <<<SIM_BLOCKS, 256>>>();
    k_batch  <<<BN, 256>>>((float*)d_out);
}